// round 14
// baseline (speedup 1.0000x reference)
#include <cuda_runtime.h>
#include <cuda_bf16.h>

// ---------------------------------------------------------------------------
// LSTM_net: 2-layer LSTM (B=256,T=512,I=64,H=256) + MLP head.
// All GEMM/LSTM operands pre-converted to tf32 bits in quad-permuted k-layout
// (applied to BOTH operands -> dot products unchanged).
//   K1 gemm_xg: cp.async (2-stage, R10-proven) -> LDS.128 -> mma.
//   K2 lstm_layer: persistent 128 CTAs; 16 groups(16 rows) x 8 slices; W_hh
//      in registers; counter barrier (red.add.release / acquire poll).
//      Layer 0 stores h ONCE (hseq only; reload from hseq[t-1]).
//   K3 head: tiny MLP.
// ---------------------------------------------------------------------------

#define BATCH  256
#define SEQ    512
#define INP    64
#define HID    256
#define GATE4  1024
#define NGROUP 16
#define GROWS  16
#define NSLICE 8
#define JCOLS  32

// Scratch (static device globals; allocation-free per harness rules)
__device__ float    g_xg  [(size_t)BATCH * SEQ * GATE4];
__device__ unsigned g_hseq[(size_t)BATCH * SEQ * HID];   // tf32 bits, permuted
__device__ unsigned g_xtf [(size_t)BATCH * SEQ * INP];   // x as tf32 bits, permuted
__device__ unsigned g_wtf [GATE4 * HID];                 // W_ih as tf32 bits, permuted
__device__ unsigned g_hbuf[2 * BATCH * HID];             // ping-pong h, tf32 bits, permuted
__device__ unsigned g_cnt [NGROUP * 32];                 // counters, 128B apart

// ---------------- helpers ----------------
__device__ __forceinline__ unsigned f2tf(float f) {
    unsigned u;
    asm("cvt.rna.tf32.f32 %0, %1;" : "=r"(u) : "f"(f));
    return u;
}
__device__ __forceinline__ void mma_tf32(float d[4],
                                         unsigned a0, unsigned a1, unsigned a2, unsigned a3,
                                         unsigned b0, unsigned b1) {
    asm volatile(
        "mma.sync.aligned.m16n8k8.row.col.f32.tf32.tf32.f32 "
        "{%0,%1,%2,%3}, {%4,%5,%6,%7}, {%8,%9}, {%0,%1,%2,%3};"
        : "+f"(d[0]), "+f"(d[1]), "+f"(d[2]), "+f"(d[3])
        : "r"(a0), "r"(a1), "r"(a2), "r"(a3), "r"(b0), "r"(b1));
}
__device__ __forceinline__ float sigf(float x) { return 1.0f / (1.0f + __expf(-x)); }
__device__ __forceinline__ float tanh_fast(float x) { return 2.0f * sigf(2.0f * x) - 1.0f; }
__device__ __forceinline__ int pquad(int i) {      // permuted pos within 16-word block
    return 4 * ((i & 7) >> 1) + 2 * (i >> 3) + (i & 1);
}
__device__ __forceinline__ void cp_async16(unsigned dst_smem, const void* src) {
    asm volatile("cp.async.cg.shared.global [%0], [%1], 16;"
                 :: "r"(dst_smem), "l"(src) : "memory");
}
__device__ __forceinline__ void cp_commit() { asm volatile("cp.async.commit_group;" ::: "memory"); }
__device__ __forceinline__ void cp_wait0()  { asm volatile("cp.async.wait_group 0;" ::: "memory"); }
__device__ __forceinline__ void cp_wait1()  { asm volatile("cp.async.wait_group 1;" ::: "memory"); }

__device__ __forceinline__ void red_add_release(unsigned* p) {
    asm volatile("red.global.add.release.gpu.u32 [%0], %1;" :: "l"(p), "r"(1u) : "memory");
}
__device__ __forceinline__ unsigned ld_acquire(const unsigned* p) {
    unsigned v;
    asm volatile("ld.global.acquire.gpu.u32 %0, [%1];" : "=r"(v) : "l"(p) : "memory");
    return v;
}

__global__ void reset_sync_kernel() {
    if (threadIdx.x < NGROUP * 32) g_cnt[threadIdx.x] = 0u;
}

// ---------------------------------------------------------------------------
// K-1: convert fp32 -> tf32 bits with quad permutation along K (row-major).
// ---------------------------------------------------------------------------
__global__ void __launch_bounds__(256) convert_tf_kernel(
    const float* __restrict__ src, unsigned* __restrict__ dst, int K, long total)
{
    for (long i = (long)blockIdx.x * blockDim.x + threadIdx.x; i < total;
         i += (long)gridDim.x * blockDim.x) {
        long row = i / K;
        int  k   = (int)(i - row * K);
        int  pk  = (k & ~15) + pquad(k & 15);
        dst[row * K + pk] = f2tf(src[i]);
    }
}

// ---------------------------------------------------------------------------
// K1 v4 (R10-proven): C[M,1024] = A[M,K] @ W[1024,K]^T + (bih+bhh)
// CTA 128x64, BK=32, 8 warps = 4(m)x2(n), warp tile 32x32. 2-stage cp.async.
// ---------------------------------------------------------------------------
#define AST  48
#define TBUF (192 * AST)
#define GEMM_SMEM (2 * TBUF * 4)       // 73728 bytes -> 2 CTAs/SM

__global__ void __launch_bounds__(256, 2) gemm_xg_kernel(
    const unsigned* __restrict__ A, const unsigned* __restrict__ W,
    const float* __restrict__ bih, const float* __restrict__ bhh,
    float* __restrict__ C, int K)
{
    extern __shared__ unsigned gsm[];

    const int tid  = threadIdx.x;
    const int lane = tid & 31;
    const int warp = tid >> 5;
    const int wm   = (warp >> 1) * 32;      // 4 m-warps
    const int wn   = (warp & 1) * 32;       // 2 n-warps
    const int  n0  = blockIdx.x * 64;       // n fast-varying (W reuse in L2)
    const long m0  = (long)blockIdx.y * 128;

    auto issueTile = [&](int buf, int k0) {
        unsigned sb = (unsigned)__cvta_generic_to_shared(gsm + buf * TBUF);
        #pragma unroll
        for (int i = 0; i < 4; i++) {                     // A: 128 rows x 8 chunks
            int q = tid + 256 * i, row = q >> 3, ch = q & 7;
            cp_async16(sb + (row * AST + ch * 4) * 4,
                       A + (m0 + row) * (long)K + k0 + ch * 4);
        }
        #pragma unroll
        for (int i = 0; i < 2; i++) {                     // B: 64 rows x 8 chunks
            int q = tid + 256 * i, row = q >> 3, ch = q & 7;
            cp_async16(sb + ((128 + row) * AST + ch * 4) * 4,
                       W + (long)(n0 + row) * K + k0 + ch * 4);
        }
        cp_commit();
    };

    float d[2][4][4] = {};
    const int gp  = lane >> 2;
    const int tg  = lane & 3;
    const int tg2 = tg * 2;

    auto compute = [&](int buf) {
        const unsigned* Ab = gsm + buf * TBUF;
        const unsigned* Bb = Ab + 128 * AST;
        #pragma unroll
        for (int m = 0; m < 2; m++) {
            const int kb = m * 16 + 4 * tg;
            uint4 a[2][2];
            #pragma unroll
            for (int r = 0; r < 2; r++) {
                a[r][0] = *reinterpret_cast<const uint4*>(&Ab[(wm + 16 * r + gp    ) * AST + kb]);
                a[r][1] = *reinterpret_cast<const uint4*>(&Ab[(wm + 16 * r + gp + 8) * AST + kb]);
            }
            #pragma unroll
            for (int j = 0; j < 4; j++) {
                uint4 b = *reinterpret_cast<const uint4*>(&Bb[(wn + 8 * j + gp) * AST + kb]);
                #pragma unroll
                for (int r = 0; r < 2; r++) {
                    mma_tf32(d[r][j], a[r][0].x, a[r][1].x, a[r][0].y, a[r][1].y, b.x, b.y);
                    mma_tf32(d[r][j], a[r][0].z, a[r][1].z, a[r][0].w, a[r][1].w, b.z, b.w);
                }
            }
        }
    };

    issueTile(0, 0);
    int cur = 0;
    for (int k0 = 0; k0 < K; k0 += 32) {
        const bool more = (k0 + 32) < K;
        if (more) { issueTile(cur ^ 1, k0 + 32); cp_wait1(); } else { cp_wait0(); }
        __syncthreads();
        compute(cur);
        __syncthreads();
        cur ^= 1;
    }

    #pragma unroll
    for (int r = 0; r < 2; r++) {
        const int row = wm + 16 * r + gp;
        #pragma unroll
        for (int j = 0; j < 4; j++) {
            int c = n0 + wn + 8 * j + tg2;
            float bi0 = bih[c] + bhh[c];
            float bi1 = bih[c + 1] + bhh[c + 1];
            C[(m0 + row    ) * GATE4 + c    ] = d[r][j][0] + bi0;
            C[(m0 + row    ) * GATE4 + c + 1] = d[r][j][1] + bi1;
            C[(m0 + row + 8) * GATE4 + c    ] = d[r][j][2] + bi0;
            C[(m0 + row + 8) * GATE4 + c + 1] = d[r][j][3] + bi1;
        }
    }
}

// ---------------------------------------------------------------------------
// K2: persistent LSTM layer. 128 CTAs = 16 batch-groups x 8 slices.
// W fragments in registers; h reloaded via cp.async.cg (4 x 16B per thread).
// Layer 0 (store_all=1): h stored ONCE into hseq; reload from hseq[t-1].
// Layer 1: hbuf ping-pong. Barrier: red.add counter (measured best).
// ---------------------------------------------------------------------------
#define WSTR 272   // 272 % 32 == 16 -> conflict-free LDS.128
#define GSTR 132
#define SMEM_REC ((GROWS * WSTR + GROWS * GSTR + GROWS * JCOLS) * 4)

__device__ __forceinline__ void group_arrive(int group) {
    __syncthreads();
    if (threadIdx.x == 0) red_add_release(&g_cnt[group * 32]);
}
__device__ __forceinline__ void group_wait(int group, unsigned target) {
    if (threadIdx.x == 0) {
        while ((int)(ld_acquire(&g_cnt[group * 32]) - target) < 0) { }
    }
    __syncthreads();
}

__global__ void __launch_bounds__(256, 1) lstm_layer_kernel(
    const float* __restrict__ xg, const float* __restrict__ Whh,
    unsigned* __restrict__ hseq, unsigned* __restrict__ hbuf, int store_all)
{
    extern __shared__ unsigned smem[];
    unsigned* Hs = smem;                          // [16][WSTR] h_prev (tf32, permuted)
    float*    Gs = (float*)(smem + GROWS * WSTR); // [16][GSTR] gate pre-acts
    float*    Cs = Gs + GROWS * GSTR;             // [16*32]    cell state

    const int tid   = threadIdx.x;
    const int lane  = tid & 31;
    const int warp  = tid >> 5;
    const int group = blockIdx.x >> 3;
    const int slice = blockIdx.x & 7;
    const int b0    = group * GROWS;
    const int j0    = slice * JCOLS;
    const int wn    = warp * 16;
    const int gp    = lane >> 2;
    const int tg    = lane & 3;
    const int tg2   = tg * 2;

    // ---- load W fragments into registers (once; step-invariant) ----
    uint4 wreg[16][2];
    #pragma unroll
    for (int m = 0; m < 16; m++) {
        #pragma unroll
        for (int nf = 0; nf < 2; nf++) {
            int rl = wn + nf * 8 + gp;
            int gr = (rl >> 5) * 256 + j0 + (rl & 31);
            const float* wp = Whh + gr * 256 + 16 * m;
            float2 lo = *reinterpret_cast<const float2*>(wp + 2 * tg);      // kf even
            float2 hi = *reinterpret_cast<const float2*>(wp + 8 + 2 * tg);  // kf odd
            wreg[m][nf] = make_uint4(f2tf(lo.x), f2tf(lo.y), f2tf(hi.x), f2tf(hi.y));
        }
    }

    // zero cell state + our slice of hbuf buffer 0 (t=0 source for both layers)
    for (int e = tid; e < GROWS * JCOLS; e += 256) {
        Cs[e] = 0.0f;
        int bl = e >> 5, j = e & 31;
        hbuf[(b0 + bl) * HID + j0 + j] = 0u;
    }
    group_arrive(group);

    const int ebl0 = tid >> 5;            // 0..7
    const int ej   = tid & 31;
    const int ejp  = (ej & ~15) + pquad(ej & 15);   // permuted column offset

    const unsigned sH = (unsigned)__cvta_generic_to_shared(Hs);

    for (int t = 0; t < SEQ; t++) {
        unsigned* hdst = hbuf + ((t + 1) & 1) * (BATCH * HID);

        // reload source for h(t): layer0 -> hseq[t-1] (single-store), t=0 -> zeros
        const unsigned* srcbase;
        long rstride;
        if (store_all) {
            if (t == 0) { srcbase = hbuf;                       rstride = HID; }
            else        { srcbase = hseq + (long)(t - 1) * HID; rstride = (long)SEQ * HID; }
        } else {
            srcbase = hbuf + (t & 1) * (BATCH * HID);           rstride = HID;
        }

        // prefetch xg for this step (independent of the barrier)
        float xr[8];
        #pragma unroll
        for (int rr = 0; rr < 2; rr++) {
            int bl = ebl0 + rr * 8;
            long xbase = ((long)(b0 + bl) * SEQ + t) * GATE4 + j0 + ej;
            xr[rr * 4 + 0] = __ldg(&xg[xbase      ]);
            xr[rr * 4 + 1] = __ldg(&xg[xbase + 256]);
            xr[rr * 4 + 2] = __ldg(&xg[xbase + 512]);
            xr[rr * 4 + 3] = __ldg(&xg[xbase + 768]);
        }

        group_wait(group, (unsigned)(t + 1) * NSLICE);

        // reload h_prev: 4 cp.async.cg 16B per thread (L2-only, pre-permuted)
        #pragma unroll
        for (int i = 0; i < 4; i++) {
            int q = tid + 256 * i;            // 0..1023
            int r = q >> 6;                   // 0..15
            int c = q & 63;                   // 16B chunks per row
            cp_async16(sH + (r * WSTR + c * 4) * 4,
                       srcbase + (b0 + r) * rstride + c * 4);
        }
        cp_commit();
        cp_wait0();
        __syncthreads();

        float d[2][4] = {}, e2[2][4] = {};
        #pragma unroll
        for (int m = 0; m < 16; m++) {
            const int kb = m * 16 + 4 * tg;
            uint4 va = *reinterpret_cast<const uint4*>(&Hs[ gp      * WSTR + kb]);
            uint4 vb = *reinterpret_cast<const uint4*>(&Hs[(gp + 8) * WSTR + kb]);
            #pragma unroll
            for (int nf = 0; nf < 2; nf++) {
                mma_tf32(d[nf],  va.x, vb.x, va.y, vb.y, wreg[m][nf].x, wreg[m][nf].y);
                mma_tf32(e2[nf], va.z, vb.z, va.w, vb.w, wreg[m][nf].z, wreg[m][nf].w);
            }
        }

        // stage gate pre-activations (sum the split accumulators here)
        #pragma unroll
        for (int nf = 0; nf < 2; nf++) {
            int c = wn + nf * 8 + tg2;
            Gs[ gp      * GSTR + c    ] = d[nf][0] + e2[nf][0];
            Gs[ gp      * GSTR + c + 1] = d[nf][1] + e2[nf][1];
            Gs[(gp + 8) * GSTR + c    ] = d[nf][2] + e2[nf][2];
            Gs[(gp + 8) * GSTR + c + 1] = d[nf][3] + e2[nf][3];
        }
        __syncthreads();

        // gate nonlinearity + state update: 2 (b,j) cells per thread
        #pragma unroll
        for (int rr = 0; rr < 2; rr++) {
            int bl = ebl0 + rr * 8;
            float gi = Gs[bl * GSTR +      ej] + xr[rr * 4 + 0];
            float gf = Gs[bl * GSTR + 32 + ej] + xr[rr * 4 + 1];
            float gg = Gs[bl * GSTR + 64 + ej] + xr[rr * 4 + 2];
            float go = Gs[bl * GSTR + 96 + ej] + xr[rr * 4 + 3];
            float si = sigf(gi), sf = sigf(gf), so = sigf(go);
            float cv = sf * Cs[bl * JCOLS + ej] + si * tanh_fast(gg);
            Cs[bl * JCOLS + ej] = cv;
            unsigned hb = f2tf(so * tanh_fast(cv));
            if (store_all) {
                // single store: hseq is both output and next-step reload source
                hseq[((long)(b0 + bl) * SEQ + t) * HID + j0 + ejp] = hb;
            } else {
                hdst[(b0 + bl) * HID + j0 + ejp] = hb;
                if (t == SEQ - 1)
                    hseq[((long)(b0 + bl) * SEQ + t) * HID + j0 + ejp] = hb;
            }
        }
        group_arrive(group);
    }
}

// ---------------------------------------------------------------------------
// K3: head. out[b, :] = tanh(h_last @ W1^T + b1) @ W2^T + b2
// hseq holds permuted tf32 bits -> unpermute + cast on load.
// ---------------------------------------------------------------------------
__global__ void __launch_bounds__(128) head_kernel(
    const unsigned* __restrict__ hseq,
    const float* __restrict__ W1, const float* __restrict__ b1,
    const float* __restrict__ W2, const float* __restrict__ b2,
    float* __restrict__ out)
{
    __shared__ float hl[256];
    __shared__ float z[128];
    const int b = blockIdx.x, tid = threadIdx.x;

    for (int i = tid; i < 256; i += 128) {
        int pi = (i & ~15) + pquad(i & 15);
        hl[i] = __uint_as_float(hseq[((long)b * SEQ + (SEQ - 1)) * HID + pi]);
    }
    __syncthreads();

    {
        float acc = b1[tid];
        const float* w = W1 + tid * 256;
        #pragma unroll 8
        for (int h = 0; h < 256; h++) acc += hl[h] * w[h];
        z[tid] = tanhf(acc);
    }
    __syncthreads();

    if (tid < 96) {
        float acc = b2[tid];
        const float* w = W2 + tid * 128;
        #pragma unroll 8
        for (int l = 0; l < 128; l++) acc += z[l] * w[l];
        out[b * 96 + tid] = acc;
    }
}

// ---------------------------------------------------------------------------
extern "C" void kernel_launch(void* const* d_in, const int* in_sizes, int n_in,
                              void* d_out, int out_size)
{
    const float* x    = (const float*)d_in[0];
    const float* Wih0 = (const float*)d_in[1];
    const float* Whh0 = (const float*)d_in[2];
    const float* bih0 = (const float*)d_in[3];
    const float* bhh0 = (const float*)d_in[4];
    const float* Wih1 = (const float*)d_in[5];
    const float* Whh1 = (const float*)d_in[6];
    const float* bih1 = (const float*)d_in[7];
    const float* bhh1 = (const float*)d_in[8];
    const float* W1   = (const float*)d_in[9];
    const float* b1   = (const float*)d_in[10];
    const float* W2   = (const float*)d_in[11];
    const float* b2   = (const float*)d_in[12];
    float* out = (float*)d_out;

    float *xg; unsigned *hseq, *xtf, *wtf, *hbuf;
    cudaGetSymbolAddress((void**)&xg,   g_xg);
    cudaGetSymbolAddress((void**)&hseq, g_hseq);
    cudaGetSymbolAddress((void**)&xtf,  g_xtf);
    cudaGetSymbolAddress((void**)&wtf,  g_wtf);
    cudaGetSymbolAddress((void**)&hbuf, g_hbuf);

    cudaFuncSetAttribute((const void*)lstm_layer_kernel,
                         cudaFuncAttributeMaxDynamicSharedMemorySize, SMEM_REC);
    cudaFuncSetAttribute((const void*)gemm_xg_kernel,
                         cudaFuncAttributeMaxDynamicSharedMemorySize, GEMM_SMEM);

    dim3 gg(GATE4 / 64, (BATCH * SEQ) / 128);

    // pre-convert x and W_ih0 (tf32 bits, quad-permuted along K)
    convert_tf_kernel<<<512, 256>>>(x, xtf, INP, (long)BATCH * SEQ * INP);
    convert_tf_kernel<<<64, 256>>>(Wih0, wtf, INP, (long)GATE4 * INP);

    // layer 0
    gemm_xg_kernel<<<gg, 256, GEMM_SMEM>>>(xtf, wtf, bih0, bhh0, xg, INP);
    reset_sync_kernel<<<1, NGROUP * 32>>>();
    lstm_layer_kernel<<<NGROUP * NSLICE, 256, SMEM_REC>>>(xg, Whh0, hseq, hbuf, 1);

    // layer 1 (A = hseq already tf32-permuted; convert W_ih1)
    convert_tf_kernel<<<256, 256>>>(Wih1, wtf, HID, (long)GATE4 * HID);
    gemm_xg_kernel<<<gg, 256, GEMM_SMEM>>>(hseq, wtf, bih1, bhh1, xg, HID);
    reset_sync_kernel<<<1, NGROUP * 32>>>();
    lstm_layer_kernel<<<NGROUP * NSLICE, 256, SMEM_REC>>>(xg, Whh1, hseq, hbuf, 0);

    // head
    head_kernel<<<BATCH, 128>>>(hseq, W1, b1, W2, b2, out);
}

// round 16
// speedup vs baseline: 1.0737x; 1.0737x over previous
#include <cuda_runtime.h>
#include <cuda_bf16.h>

// ---------------------------------------------------------------------------
// LSTM_net: 2-layer LSTM (B=256,T=512,I=64,H=256) + MLP head.
// Operands tf32-bit, quad-permuted along K (both sides -> dot unchanged).
//   K1 gemm_xg: R10-proven 2-stage cp.async mma.sync GEMM (layer-0 input only).
//   K2 lstm_layer (mode 0 = layer 0): R10 recurrent step; AFTER each arrive,
//      computes xg1(t-1) = W_ih1_slice @ Hs in the barrier-propagation slack
//      (W_ih1 slice resident in SMEM, quad-permuted) -> g_xg1. gemm1 deleted.
//   K2 (mode 1 = layer 1): reads g_xg1, adds biases in epilogue.
//   K3 head: tiny MLP.
// NOTE: tcgen05 unavailable (harness targets sm_100, not sm_100a).
// ---------------------------------------------------------------------------

#define BATCH  256
#define SEQ    512
#define INP    64
#define HID    256
#define GATE4  1024
#define NGROUP 16
#define GROWS  16
#define NSLICE 8
#define JCOLS  32

__device__ float    g_xg  [(size_t)BATCH * SEQ * GATE4];  // layer-0 gate inputs (bias baked)
__device__ float    g_xg1 [(size_t)BATCH * SEQ * GATE4];  // layer-1 gate inputs (no bias)
__device__ unsigned g_hseq[(size_t)BATCH * SEQ * HID];    // tf32 bits, permuted (head input)
__device__ unsigned g_xtf [(size_t)BATCH * SEQ * INP];
__device__ unsigned g_wtf [GATE4 * HID];
__device__ unsigned g_hbuf[2 * BATCH * HID];              // ping-pong h
__device__ unsigned g_cnt [NGROUP * 32];

// ---------------- helpers ----------------
__device__ __forceinline__ unsigned f2tf(float f) {
    unsigned u;
    asm("cvt.rna.tf32.f32 %0, %1;" : "=r"(u) : "f"(f));
    return u;
}
__device__ __forceinline__ void mma_tf32(float d[4],
                                         unsigned a0, unsigned a1, unsigned a2, unsigned a3,
                                         unsigned b0, unsigned b1) {
    asm volatile(
        "mma.sync.aligned.m16n8k8.row.col.f32.tf32.tf32.f32 "
        "{%0,%1,%2,%3}, {%4,%5,%6,%7}, {%8,%9}, {%0,%1,%2,%3};"
        : "+f"(d[0]), "+f"(d[1]), "+f"(d[2]), "+f"(d[3])
        : "r"(a0), "r"(a1), "r"(a2), "r"(a3), "r"(b0), "r"(b1));
}
__device__ __forceinline__ float sigf(float x) { return 1.0f / (1.0f + __expf(-x)); }
__device__ __forceinline__ float tanh_fast(float x) { return 2.0f * sigf(2.0f * x) - 1.0f; }
__device__ __forceinline__ int pquad(int i) {
    return 4 * ((i & 7) >> 1) + 2 * (i >> 3) + (i & 1);
}
__device__ __forceinline__ void cp_async16(unsigned dst_smem, const void* src) {
    asm volatile("cp.async.cg.shared.global [%0], [%1], 16;"
                 :: "r"(dst_smem), "l"(src) : "memory");
}
__device__ __forceinline__ void cp_commit() { asm volatile("cp.async.commit_group;" ::: "memory"); }
__device__ __forceinline__ void cp_wait0()  { asm volatile("cp.async.wait_group 0;" ::: "memory"); }
__device__ __forceinline__ void cp_wait1()  { asm volatile("cp.async.wait_group 1;" ::: "memory"); }

__device__ __forceinline__ void red_add_release(unsigned* p) {
    asm volatile("red.global.add.release.gpu.u32 [%0], %1;" :: "l"(p), "r"(1u) : "memory");
}
__device__ __forceinline__ unsigned ld_acquire(const unsigned* p) {
    unsigned v;
    asm volatile("ld.global.acquire.gpu.u32 %0, [%1];" : "=r"(v) : "l"(p) : "memory");
    return v;
}

__global__ void reset_sync_kernel() {
    if (threadIdx.x < NGROUP * 32) g_cnt[threadIdx.x] = 0u;
}

// ---------------------------------------------------------------------------
// K-1: convert fp32 -> tf32 bits with quad permutation along K.
// ---------------------------------------------------------------------------
__global__ void __launch_bounds__(256) convert_tf_kernel(
    const float* __restrict__ src, unsigned* __restrict__ dst, int K, long total)
{
    for (long i = (long)blockIdx.x * blockDim.x + threadIdx.x; i < total;
         i += (long)gridDim.x * blockDim.x) {
        long row = i / K;
        int  k   = (int)(i - row * K);
        int  pk  = (k & ~15) + pquad(k & 15);
        dst[row * K + pk] = f2tf(src[i]);
    }
}

// ---------------------------------------------------------------------------
// K1 (R10-proven): C[M,1024] = A[M,K] @ W[1024,K]^T + (bih+bhh)
// ---------------------------------------------------------------------------
#define AST  48
#define TBUF (192 * AST)
#define GEMM_SMEM (2 * TBUF * 4)

__global__ void __launch_bounds__(256, 2) gemm_xg_kernel(
    const unsigned* __restrict__ A, const unsigned* __restrict__ W,
    const float* __restrict__ bih, const float* __restrict__ bhh,
    float* __restrict__ C, int K)
{
    extern __shared__ unsigned gsm[];

    const int tid  = threadIdx.x;
    const int lane = tid & 31;
    const int warp = tid >> 5;
    const int wm   = (warp >> 1) * 32;
    const int wn   = (warp & 1) * 32;
    const int  n0  = blockIdx.x * 64;
    const long m0  = (long)blockIdx.y * 128;

    auto issueTile = [&](int buf, int k0) {
        unsigned sb = (unsigned)__cvta_generic_to_shared(gsm + buf * TBUF);
        #pragma unroll
        for (int i = 0; i < 4; i++) {
            int q = tid + 256 * i, row = q >> 3, ch = q & 7;
            cp_async16(sb + (row * AST + ch * 4) * 4,
                       A + (m0 + row) * (long)K + k0 + ch * 4);
        }
        #pragma unroll
        for (int i = 0; i < 2; i++) {
            int q = tid + 256 * i, row = q >> 3, ch = q & 7;
            cp_async16(sb + ((128 + row) * AST + ch * 4) * 4,
                       W + (long)(n0 + row) * K + k0 + ch * 4);
        }
        cp_commit();
    };

    float d[2][4][4] = {};
    const int gp  = lane >> 2;
    const int tg  = lane & 3;
    const int tg2 = tg * 2;

    auto compute = [&](int buf) {
        const unsigned* Ab = gsm + buf * TBUF;
        const unsigned* Bb = Ab + 128 * AST;
        #pragma unroll
        for (int m = 0; m < 2; m++) {
            const int kb = m * 16 + 4 * tg;
            uint4 a[2][2];
            #pragma unroll
            for (int r = 0; r < 2; r++) {
                a[r][0] = *reinterpret_cast<const uint4*>(&Ab[(wm + 16 * r + gp    ) * AST + kb]);
                a[r][1] = *reinterpret_cast<const uint4*>(&Ab[(wm + 16 * r + gp + 8) * AST + kb]);
            }
            #pragma unroll
            for (int j = 0; j < 4; j++) {
                uint4 b = *reinterpret_cast<const uint4*>(&Bb[(wn + 8 * j + gp) * AST + kb]);
                #pragma unroll
                for (int r = 0; r < 2; r++) {
                    mma_tf32(d[r][j], a[r][0].x, a[r][1].x, a[r][0].y, a[r][1].y, b.x, b.y);
                    mma_tf32(d[r][j], a[r][0].z, a[r][1].z, a[r][0].w, a[r][1].w, b.z, b.w);
                }
            }
        }
    };

    issueTile(0, 0);
    int cur = 0;
    for (int k0 = 0; k0 < K; k0 += 32) {
        const bool more = (k0 + 32) < K;
        if (more) { issueTile(cur ^ 1, k0 + 32); cp_wait1(); } else { cp_wait0(); }
        __syncthreads();
        compute(cur);
        __syncthreads();
        cur ^= 1;
    }

    #pragma unroll
    for (int r = 0; r < 2; r++) {
        const int row = wm + 16 * r + gp;
        #pragma unroll
        for (int j = 0; j < 4; j++) {
            int c = n0 + wn + 8 * j + tg2;
            float bi0 = bih[c] + bhh[c];
            float bi1 = bih[c + 1] + bhh[c + 1];
            C[(m0 + row    ) * GATE4 + c    ] = d[r][j][0] + bi0;
            C[(m0 + row    ) * GATE4 + c + 1] = d[r][j][1] + bi1;
            C[(m0 + row + 8) * GATE4 + c    ] = d[r][j][2] + bi0;
            C[(m0 + row + 8) * GATE4 + c + 1] = d[r][j][3] + bi1;
        }
    }
}

// ---------------------------------------------------------------------------
// K2: persistent LSTM layer. 128 CTAs = 16 batch-groups x 8 slices.
// mode 0 (layer 0): after each arrive, computes xg1(t-1) = Wi_slice @ Hs in
//   the barrier-propagation slack; Wi slice in SMEM (quad-permuted rows).
// mode 1 (layer 1): reads xg1, adds biases in epilogue; stores hseq[SEQ-1].
// ---------------------------------------------------------------------------
#define WSTR 272   // 272 % 32 == 16 -> conflict-free LDS.128
#define GSTR 132
#define WI_OFF  (GROWS * WSTR + GROWS * GSTR + GROWS * JCOLS)   // words
#define SMEM_REC ((WI_OFF + 128 * WSTR) * 4)                    // ~167 KB

__device__ __forceinline__ void group_arrive(int group) {
    __syncthreads();
    if (threadIdx.x == 0) red_add_release(&g_cnt[group * 32]);
}
__device__ __forceinline__ void group_wait(int group, unsigned target) {
    if (threadIdx.x == 0) {
        while ((int)(ld_acquire(&g_cnt[group * 32]) - target) < 0) { }
    }
    __syncthreads();
}

__global__ void __launch_bounds__(256, 1) lstm_layer_kernel(
    const float* __restrict__ xg, const float* __restrict__ Whh,
    const float* __restrict__ Wih1, float* __restrict__ xg1out,
    const float* __restrict__ bih, const float* __restrict__ bhh,
    unsigned* __restrict__ hseq, unsigned* __restrict__ hbuf, int mode)
{
    extern __shared__ unsigned smem[];
    unsigned* Hs = smem;                          // [16][WSTR] h_prev (tf32, permuted)
    float*    Gs = (float*)(smem + GROWS * WSTR); // [16][GSTR] gate pre-acts
    float*    Cs = Gs + GROWS * GSTR;             // [16*32]    cell state
    unsigned* Wi = smem + WI_OFF;                 // [128][WSTR] W_ih1 slice (mode 0)

    const int tid   = threadIdx.x;
    const int lane  = tid & 31;
    const int warp  = tid >> 5;
    const int group = blockIdx.x >> 3;
    const int slice = blockIdx.x & 7;
    const int b0    = group * GROWS;
    const int j0    = slice * JCOLS;
    const int wn    = warp * 16;
    const int gp    = lane >> 2;
    const int tg    = lane & 3;
    const int tg2   = tg * 2;

    // ---- W_hh fragments into registers (once) ----
    uint4 wreg[16][2];
    #pragma unroll
    for (int m = 0; m < 16; m++) {
        #pragma unroll
        for (int nf = 0; nf < 2; nf++) {
            int rl = wn + nf * 8 + gp;
            int gr = (rl >> 5) * 256 + j0 + (rl & 31);
            const float* wp = Whh + gr * 256 + 16 * m;
            float2 lo = *reinterpret_cast<const float2*>(wp + 2 * tg);
            float2 hi = *reinterpret_cast<const float2*>(wp + 8 + 2 * tg);
            wreg[m][nf] = make_uint4(f2tf(lo.x), f2tf(lo.y), f2tf(hi.x), f2tf(hi.y));
        }
    }

    // ---- mode 0: W_ih1 slice into SMEM (quad-permuted); k == tid per elem ----
    if (mode == 0) {
        const int pk = (tid & ~15) + pquad(tid & 15);
        for (int rl = 0; rl < 128; rl++) {
            int gr = (rl >> 5) * 256 + j0 + (rl & 31);
            Wi[rl * WSTR + pk] = f2tf(Wih1[gr * 256 + tid]);
        }
    }

    // ---- mode 1: per-thread gate biases (col = gate*256 + j0 + ej) ----
    const int ej = tid & 31;
    float breg[4] = {0, 0, 0, 0};
    if (mode == 1) {
        #pragma unroll
        for (int g = 0; g < 4; g++) {
            int c = g * 256 + j0 + ej;
            breg[g] = bih[c] + bhh[c];
        }
    }

    // zero cell state + our slice of hbuf buffer 0
    for (int e = tid; e < GROWS * JCOLS; e += 256) {
        Cs[e] = 0.0f;
        int bl = e >> 5, j = e & 31;
        hbuf[(b0 + bl) * HID + j0 + j] = 0u;
    }
    group_arrive(group);

    const int ebl0 = tid >> 5;
    const int ejp  = (ej & ~15) + pquad(ej & 15);
    const unsigned sH = (unsigned)__cvta_generic_to_shared(Hs);

    // xg1 compute+store for time index ti from current Hs (mode 0 only)
    auto do_xg1 = [&](int ti) {
        float dx[2][4] = {}, ex[2][4] = {};
        #pragma unroll
        for (int m = 0; m < 16; m++) {
            const int kb = m * 16 + 4 * tg;
            uint4 va = *reinterpret_cast<const uint4*>(&Hs[ gp      * WSTR + kb]);
            uint4 vb = *reinterpret_cast<const uint4*>(&Hs[(gp + 8) * WSTR + kb]);
            #pragma unroll
            for (int nf = 0; nf < 2; nf++) {
                uint4 w = *reinterpret_cast<const uint4*>(&Wi[(wn + nf * 8 + gp) * WSTR + kb]);
                mma_tf32(dx[nf], va.x, vb.x, va.y, vb.y, w.x, w.y);
                mma_tf32(ex[nf], va.z, vb.z, va.w, vb.w, w.z, w.w);
            }
        }
        #pragma unroll
        for (int nf = 0; nf < 2; nf++) {
            int c = wn + nf * 8 + tg2;
            Gs[ gp      * GSTR + c    ] = dx[nf][0] + ex[nf][0];
            Gs[ gp      * GSTR + c + 1] = dx[nf][1] + ex[nf][1];
            Gs[(gp + 8) * GSTR + c    ] = dx[nf][2] + ex[nf][2];
            Gs[(gp + 8) * GSTR + c + 1] = dx[nf][3] + ex[nf][3];
        }
        __syncthreads();
        #pragma unroll
        for (int rr = 0; rr < 2; rr++) {
            int bl = ebl0 + rr * 8;
            long base = ((long)(b0 + bl) * SEQ + ti) * GATE4 + j0 + ej;
            #pragma unroll
            for (int g = 0; g < 4; g++)
                xg1out[base + g * 256] = Gs[bl * GSTR + g * 32 + ej];
        }
        __syncthreads();   // Gs free before next use
    };

    for (int t = 0; t < SEQ; t++) {
        const unsigned* hsrc = hbuf + (t & 1) * (BATCH * HID);
        unsigned*       hdst = hbuf + ((t + 1) & 1) * (BATCH * HID);

        // prefetch gate inputs for this step
        float xr[8];
        #pragma unroll
        for (int rr = 0; rr < 2; rr++) {
            int bl = ebl0 + rr * 8;
            long xbase = ((long)(b0 + bl) * SEQ + t) * GATE4 + j0 + ej;
            xr[rr * 4 + 0] = __ldg(&xg[xbase      ]);
            xr[rr * 4 + 1] = __ldg(&xg[xbase + 256]);
            xr[rr * 4 + 2] = __ldg(&xg[xbase + 512]);
            xr[rr * 4 + 3] = __ldg(&xg[xbase + 768]);
        }

        group_wait(group, (unsigned)(t + 1) * NSLICE);

        // reload h_prev: 4 cp.async.cg 16B per thread (L2-only, pre-permuted)
        #pragma unroll
        for (int i = 0; i < 4; i++) {
            int q = tid + 256 * i;
            int r = q >> 6;
            int c = q & 63;
            cp_async16(sH + (r * WSTR + c * 4) * 4,
                       hsrc + (b0 + r) * HID + c * 4);
        }
        cp_commit();
        cp_wait0();
        __syncthreads();

        float d[2][4] = {}, e2[2][4] = {};
        #pragma unroll
        for (int m = 0; m < 16; m++) {
            const int kb = m * 16 + 4 * tg;
            uint4 va = *reinterpret_cast<const uint4*>(&Hs[ gp      * WSTR + kb]);
            uint4 vb = *reinterpret_cast<const uint4*>(&Hs[(gp + 8) * WSTR + kb]);
            #pragma unroll
            for (int nf = 0; nf < 2; nf++) {
                mma_tf32(d[nf],  va.x, vb.x, va.y, vb.y, wreg[m][nf].x, wreg[m][nf].y);
                mma_tf32(e2[nf], va.z, vb.z, va.w, vb.w, wreg[m][nf].z, wreg[m][nf].w);
            }
        }

        #pragma unroll
        for (int nf = 0; nf < 2; nf++) {
            int c = wn + nf * 8 + tg2;
            Gs[ gp      * GSTR + c    ] = d[nf][0] + e2[nf][0];
            Gs[ gp      * GSTR + c + 1] = d[nf][1] + e2[nf][1];
            Gs[(gp + 8) * GSTR + c    ] = d[nf][2] + e2[nf][2];
            Gs[(gp + 8) * GSTR + c + 1] = d[nf][3] + e2[nf][3];
        }
        __syncthreads();

        #pragma unroll
        for (int rr = 0; rr < 2; rr++) {
            int bl = ebl0 + rr * 8;
            float gi = Gs[bl * GSTR +      ej] + xr[rr * 4 + 0] + breg[0];
            float gf = Gs[bl * GSTR + 32 + ej] + xr[rr * 4 + 1] + breg[1];
            float gg = Gs[bl * GSTR + 64 + ej] + xr[rr * 4 + 2] + breg[2];
            float go = Gs[bl * GSTR + 96 + ej] + xr[rr * 4 + 3] + breg[3];
            float si = sigf(gi), sf = sigf(gf), so = sigf(go);
            float cv = sf * Cs[bl * JCOLS + ej] + si * tanh_fast(gg);
            Cs[bl * JCOLS + ej] = cv;
            unsigned hb = f2tf(so * tanh_fast(cv));
            hdst[(b0 + bl) * HID + j0 + ejp] = hb;
            if (mode == 1 && t == SEQ - 1)
                hseq[((long)(b0 + bl) * SEQ + t) * HID + j0 + ejp] = hb;
        }
        group_arrive(group);

        // slack work: xg1 for time t-1 from Hs (= h0 state before x(t) = h0seq[t-1])
        if (mode == 0 && t > 0) do_xg1(t - 1);
    }

    // tail: xg1[SEQ-1] from final h0 state (hbuf[SEQ&1] == hbuf[0])
    if (mode == 0) {
        group_wait(group, (unsigned)(SEQ + 1) * NSLICE);
        const unsigned* hsrc = hbuf + (SEQ & 1) * (BATCH * HID);
        #pragma unroll
        for (int i = 0; i < 4; i++) {
            int q = tid + 256 * i;
            int r = q >> 6;
            int c = q & 63;
            cp_async16(sH + (r * WSTR + c * 4) * 4,
                       hsrc + (b0 + r) * HID + c * 4);
        }
        cp_commit();
        cp_wait0();
        __syncthreads();
        do_xg1(SEQ - 1);
    }
}

// ---------------------------------------------------------------------------
// K3: head. hseq holds permuted tf32 bits -> unpermute + cast on load.
// ---------------------------------------------------------------------------
__global__ void __launch_bounds__(128) head_kernel(
    const unsigned* __restrict__ hseq,
    const float* __restrict__ W1, const float* __restrict__ b1,
    const float* __restrict__ W2, const float* __restrict__ b2,
    float* __restrict__ out)
{
    __shared__ float hl[256];
    __shared__ float z[128];
    const int b = blockIdx.x, tid = threadIdx.x;

    for (int i = tid; i < 256; i += 128) {
        int pi = (i & ~15) + pquad(i & 15);
        hl[i] = __uint_as_float(hseq[((long)b * SEQ + (SEQ - 1)) * HID + pi]);
    }
    __syncthreads();

    {
        float acc = b1[tid];
        const float* w = W1 + tid * 256;
        #pragma unroll 8
        for (int h = 0; h < 256; h++) acc += hl[h] * w[h];
        z[tid] = tanhf(acc);
    }
    __syncthreads();

    if (tid < 96) {
        float acc = b2[tid];
        const float* w = W2 + tid * 128;
        #pragma unroll 8
        for (int l = 0; l < 128; l++) acc += z[l] * w[l];
        out[b * 96 + tid] = acc;
    }
}

// ---------------------------------------------------------------------------
extern "C" void kernel_launch(void* const* d_in, const int* in_sizes, int n_in,
                              void* d_out, int out_size)
{
    const float* x    = (const float*)d_in[0];
    const float* Wih0 = (const float*)d_in[1];
    const float* Whh0 = (const float*)d_in[2];
    const float* bih0 = (const float*)d_in[3];
    const float* bhh0 = (const float*)d_in[4];
    const float* Wih1 = (const float*)d_in[5];
    const float* Whh1 = (const float*)d_in[6];
    const float* bih1 = (const float*)d_in[7];
    const float* bhh1 = (const float*)d_in[8];
    const float* W1   = (const float*)d_in[9];
    const float* b1   = (const float*)d_in[10];
    const float* W2   = (const float*)d_in[11];
    const float* b2   = (const float*)d_in[12];
    float* out = (float*)d_out;

    float *xg, *xg1; unsigned *hseq, *xtf, *wtf, *hbuf;
    cudaGetSymbolAddress((void**)&xg,   g_xg);
    cudaGetSymbolAddress((void**)&xg1,  g_xg1);
    cudaGetSymbolAddress((void**)&hseq, g_hseq);
    cudaGetSymbolAddress((void**)&xtf,  g_xtf);
    cudaGetSymbolAddress((void**)&wtf,  g_wtf);
    cudaGetSymbolAddress((void**)&hbuf, g_hbuf);

    cudaFuncSetAttribute((const void*)lstm_layer_kernel,
                         cudaFuncAttributeMaxDynamicSharedMemorySize, SMEM_REC);
    cudaFuncSetAttribute((const void*)gemm_xg_kernel,
                         cudaFuncAttributeMaxDynamicSharedMemorySize, GEMM_SMEM);

    dim3 gg(GATE4 / 64, (BATCH * SEQ) / 128);

    // pre-convert x and W_ih0 (tf32 bits, quad-permuted along K)
    convert_tf_kernel<<<512, 256>>>(x, xtf, INP, (long)BATCH * SEQ * INP);
    convert_tf_kernel<<<64, 256>>>(Wih0, wtf, INP, (long)GATE4 * INP);

    // layer 0 input GEMM (bias baked)
    gemm_xg_kernel<<<gg, 256, GEMM_SMEM>>>(xtf, wtf, bih0, bhh0, xg, INP);

    // layer 0 LSTM — also produces xg1 (layer-1 gate inputs, no bias)
    reset_sync_kernel<<<1, NGROUP * 32>>>();
    lstm_layer_kernel<<<NGROUP * NSLICE, 256, SMEM_REC>>>(
        xg, Whh0, Wih1, xg1, bih0, bhh0, hseq, hbuf, 0);

    // layer 1 LSTM — reads xg1, adds biases in epilogue
    reset_sync_kernel<<<1, NGROUP * 32>>>();
    lstm_layer_kernel<<<NGROUP * NSLICE, 256, SMEM_REC>>>(
        xg1, Whh1, Wih1, xg1, bih1, bhh1, hseq, hbuf, 1);

    // head
    head_kernel<<<BATCH, 128>>>(hseq, W1, b1, W2, b2, out);
}